// round 15
// baseline (speedup 1.0000x reference)
#include <cuda_runtime.h>
#include <math.h>
#include <stdint.h>

#define LSEQ 256
#define VEC  256
#define HID  256
#define NR1  96      // 32 question seqs + 64 article seqs
#define NR2  64      // Beff rows
#define LD   512     // 2*HID
#define F8   2048

#define RPS   16     // rows per slab (per cluster)
#define UPC   32     // units per CTA
#define CSZ   8      // cluster size
#define HPAD  258    // padded row stride (floats) in h buffer

// ------------------- scratch (device globals; no allocs) -------------------
__device__ __align__(256) float g_X1 [LSEQ*NR1*VEC];
__device__ __align__(256) float g_GI1[LSEQ*1536*NR1];
__device__ __align__(256) float g_HS1[LSEQ*2*HID*NR1];
__device__ __align__(256) float g_CQ1[NR1*LSEQ*LD];
__device__ __align__(256) float g_CW2[NR2*LSEQ*LD];
__device__ __align__(256) float g_S  [NR2*LSEQ*LSEQ];
__device__ __align__(256) float g_CW [NR2*LSEQ];
__device__ __align__(256) float g_QW [NR2*LSEQ];
__device__ __align__(256) float g_M  [NR2*LSEQ];
__device__ __align__(256) float g_Q2C[NR2*LD];
__device__ __align__(256) float g_C2Q[NR2*LSEQ*LD];
__device__ __align__(256) float g_ATT[LSEQ*NR2*F8];
__device__ __align__(256) float g_GI2[LSEQ*1536*NR2];
__device__ __align__(256) float g_HS2[LSEQ*2*HID*NR2];
__device__ __align__(256) float g_C2 [NR2*LSEQ*LD];
__device__ __align__(256) float g_AT2[LSEQ*NR2*F8];
__device__ __align__(256) float g_PART[32*16];

// ------------------- packed fp32x2 helpers ---------------------------------
__device__ __forceinline__ void ffma2u(unsigned long long& acc,
                                       unsigned long long a, unsigned long long b) {
    asm("fma.rn.f32x2 %0, %1, %2, %0;" : "+l"(acc) : "l"(a), "l"(b));
}
__device__ __forceinline__ unsigned long long pack2u(float w) {
    unsigned long long r;
    asm("mov.b64 %0, {%1, %1};" : "=l"(r) : "f"(w));
    return r;
}

// ------------------- tf32 tensor-core helpers --------------------------------
__device__ __forceinline__ uint32_t f2tf32(float x) {
    uint32_t r; asm("cvt.rna.tf32.f32 %0, %1;" : "=r"(r) : "f"(x)); return r;
}
__device__ __forceinline__ void mma_tf32(float* c, const uint32_t* a,
                                         uint32_t b0, uint32_t b1) {
    asm volatile("mma.sync.aligned.m16n8k8.row.col.f32.tf32.tf32.f32 "
        "{%0,%1,%2,%3}, {%4,%5,%6,%7}, {%8,%9}, {%0,%1,%2,%3};"
        : "+f"(c[0]), "+f"(c[1]), "+f"(c[2]), "+f"(c[3])
        : "r"(a[0]), "r"(a[1]), "r"(a[2]), "r"(a[3]), "r"(b0), "r"(b1));
}

// ------------------- cluster helpers ----------------------------------------
__device__ __forceinline__ uint32_t smem_u32(const void* p) {
    return (uint32_t)__cvta_generic_to_shared(p);
}
__device__ __forceinline__ uint32_t mapa_u32(uint32_t addr, uint32_t rank) {
    uint32_t r;
    asm("mapa.shared::cluster.u32 %0, %1, %2;" : "=r"(r) : "r"(addr), "r"(rank));
    return r;
}
__device__ __forceinline__ void st_cluster64(uint32_t addr, float2 v) {
    asm volatile("st.shared::cluster.b64 [%0], %1;"
                 :: "r"(addr), "l"(*(unsigned long long*)&v) : "memory");
}
__device__ __forceinline__ void cluster_sync_() {
    asm volatile("barrier.cluster.arrive.aligned;" ::: "memory");
    asm volatile("barrier.cluster.wait.aligned;" ::: "memory");
}

// ------------------- embedding gather ---------------------------------------
__global__ void k_embed(const int* __restrict__ q, const int* __restrict__ a,
                        const float* __restrict__ emb)
{
    int t = blockIdx.x, r = blockIdx.y;
    int tok = (r < 32) ? q[r*LSEQ + t] : a[(r-32)*LSEQ + t];
    const float4* src = (const float4*)(emb + (size_t)tok*VEC);
    float4* dst = (float4*)(g_X1 + ((size_t)t*NR1 + r)*VEC);
    dst[threadIdx.x] = src[threadIdx.x];
}

// ------------------- tf32 TC GEMM NT (double-buffered, 1 sync/iter) ---------
// BM=128, BN=64, BK=32, 256 threads = 8 warps (4m x 2n), warp tile 32x32.
// M%128==0, K%32==0; N guarded (even N).
__global__ __launch_bounds__(256) void k_tc_nt(
    const float* __restrict__ A, const float* __restrict__ B,
    float* __restrict__ C, const float* __restrict__ bias,
    int M, int N, int K, long sA, long sB, long sC)
{
    extern __shared__ uint32_t gsm[];
    uint32_t (*As)[36] = (uint32_t(*)[36])gsm;              // [2*128][36]
    uint32_t (*Bs)[36] = (uint32_t(*)[36])(gsm + 2*128*36); // [2*64][36]
    const float* Ab = A + (size_t)blockIdx.z * sA;
    const float* Bb = B + (size_t)blockIdx.z * sB;
    float* Cb = C + (size_t)blockIdx.z * sC;
    int m0 = blockIdx.x*128, n0 = blockIdx.y*64;
    int tid = threadIdx.x, lane = tid & 31;
    int wm = ((tid>>5) & 3)*32, wn = (tid>>7)*32;
    int g = lane>>2, tg = lane&3;
    int am = tid>>3, ac = tid&7;

    float4 ra[4], rb[2];
    float acc[2][4][4];
#pragma unroll
    for (int i=0;i<2;i++)
#pragma unroll
        for (int j=0;j<4;j++)
#pragma unroll
            for (int l=0;l<4;l++) acc[i][j][l]=0.f;

    auto LDG = [&](int k0) {
#pragma unroll
        for (int p=0;p<4;p++)
            ra[p] = *(const float4*)(Ab + (size_t)(m0+am+32*p)*K + k0 + ac*4);
#pragma unroll
        for (int p=0;p<2;p++) {
            int n = n0 + am + 32*p;
            rb[p] = (n < N) ? *(const float4*)(Bb + (size_t)n*K + k0 + ac*4)
                            : make_float4(0.f,0.f,0.f,0.f);
        }
    };
    auto STS = [&](int b) {
#pragma unroll
        for (int p=0;p<4;p++) {
            uint4 v = {f2tf32(ra[p].x),f2tf32(ra[p].y),f2tf32(ra[p].z),f2tf32(ra[p].w)};
            *(uint4*)&As[b*128 + am+32*p][ac*4] = v;
        }
#pragma unroll
        for (int p=0;p<2;p++) {
            uint4 v = {f2tf32(rb[p].x),f2tf32(rb[p].y),f2tf32(rb[p].z),f2tf32(rb[p].w)};
            *(uint4*)&Bs[b*64 + am+32*p][ac*4] = v;
        }
    };
    auto COMPUTE = [&](int b) {
#pragma unroll
        for (int ks=0;ks<4;ks++) {
            uint32_t a[2][4];
#pragma unroll
            for (int mi=0;mi<2;mi++) {
                int r = b*128 + wm + mi*16 + g, c = ks*8 + tg;
                a[mi][0]=As[r][c];   a[mi][1]=As[r+8][c];
                a[mi][2]=As[r][c+4]; a[mi][3]=As[r+8][c+4];
            }
#pragma unroll
            for (int ni=0;ni<4;ni++) {
                int bn = b*64 + wn + ni*8 + g, bk = ks*8 + tg;
                uint32_t b0=Bs[bn][bk], b1=Bs[bn][bk+4];
                mma_tf32(acc[0][ni], a[0], b0, b1);
                mma_tf32(acc[1][ni], a[1], b0, b1);
            }
        }
    };

    LDG(0); STS(0); __syncthreads();
    int cur = 0;
    for (int k0 = 32; k0 < K; k0 += 32) {
        LDG(k0);
        COMPUTE(cur);
        STS(cur^1);
        __syncthreads();
        cur ^= 1;
    }
    COMPUTE(cur);

#pragma unroll
    for (int mi=0;mi<2;mi++) {
        int row = m0 + wm + mi*16 + g;
        float b0v = bias ? bias[row]   : 0.f;
        float b8v = bias ? bias[row+8] : 0.f;
#pragma unroll
        for (int ni=0;ni<4;ni++) {
            int col = n0 + wn + ni*8 + tg*2;
            if (col < N) {
                float2 v0 = {acc[mi][ni][0] + b0v, acc[mi][ni][1] + b0v};
                float2 v1 = {acc[mi][ni][2] + b8v, acc[mi][ni][3] + b8v};
                *(float2*)(Cb + (size_t)row*N + col) = v0;
                *(float2*)(Cb + (size_t)(row+8)*N + col) = v1;
            }
        }
    }
}

// ------------------- tf32 TC GEMM NN (double-buffered, 1 sync/iter) ---------
// BM=128, BN=64, BK=32. M%128==0, N%64==0, K%32==0.
__global__ __launch_bounds__(256) void k_tc_nn(
    const float* __restrict__ A, const float* __restrict__ B,
    float* __restrict__ C,
    int M, int N, int K, long sA, long sB, long sC)
{
    extern __shared__ uint32_t gsm[];
    uint32_t (*As)[36] = (uint32_t(*)[36])gsm;              // [2*128][36]
    uint32_t (*Bs)[72] = (uint32_t(*)[72])(gsm + 2*128*36); // [2*32][72]
    const float* Ab = A + (size_t)blockIdx.z * sA;
    const float* Bb = B + (size_t)blockIdx.z * sB;
    float* Cb = C + (size_t)blockIdx.z * sC;
    int m0 = blockIdx.x*128, n0 = blockIdx.y*64;
    int tid = threadIdx.x, lane = tid & 31;
    int wm = ((tid>>5) & 3)*32, wn = (tid>>7)*32;
    int g = lane>>2, tg = lane&3;
    int am = tid>>3, ac = tid&7;
    int bk = tid>>4, bc = tid&15;

    float4 ra[4], rb[2];
    float acc[2][4][4];
#pragma unroll
    for (int i=0;i<2;i++)
#pragma unroll
        for (int j=0;j<4;j++)
#pragma unroll
            for (int l=0;l<4;l++) acc[i][j][l]=0.f;

    auto LDG = [&](int k0) {
#pragma unroll
        for (int p=0;p<4;p++)
            ra[p] = *(const float4*)(Ab + (size_t)(m0+am+32*p)*K + k0 + ac*4);
#pragma unroll
        for (int p=0;p<2;p++)
            rb[p] = *(const float4*)(Bb + (size_t)(k0+bk+16*p)*N + n0 + bc*4);
    };
    auto STS = [&](int b) {
#pragma unroll
        for (int p=0;p<4;p++) {
            uint4 v = {f2tf32(ra[p].x),f2tf32(ra[p].y),f2tf32(ra[p].z),f2tf32(ra[p].w)};
            *(uint4*)&As[b*128 + am+32*p][ac*4] = v;
        }
#pragma unroll
        for (int p=0;p<2;p++) {
            uint4 v = {f2tf32(rb[p].x),f2tf32(rb[p].y),f2tf32(rb[p].z),f2tf32(rb[p].w)};
            *(uint4*)&Bs[b*32 + bk+16*p][bc*4] = v;
        }
    };
    auto COMPUTE = [&](int b) {
#pragma unroll
        for (int ks=0;ks<4;ks++) {
            uint32_t a[2][4];
#pragma unroll
            for (int mi=0;mi<2;mi++) {
                int r = b*128 + wm + mi*16 + g, c = ks*8 + tg;
                a[mi][0]=As[r][c];   a[mi][1]=As[r+8][c];
                a[mi][2]=As[r][c+4]; a[mi][3]=As[r+8][c+4];
            }
#pragma unroll
            for (int ni=0;ni<4;ni++) {
                int bn = wn + ni*8 + g;
                uint32_t b0=Bs[b*32 + ks*8+tg][bn], b1=Bs[b*32 + ks*8+tg+4][bn];
                mma_tf32(acc[0][ni], a[0], b0, b1);
                mma_tf32(acc[1][ni], a[1], b0, b1);
            }
        }
    };

    LDG(0); STS(0); __syncthreads();
    int cur = 0;
    for (int k0 = 32; k0 < K; k0 += 32) {
        LDG(k0);
        COMPUTE(cur);
        STS(cur^1);
        __syncthreads();
        cur ^= 1;
    }
    COMPUTE(cur);

#pragma unroll
    for (int mi=0;mi<2;mi++) {
        int row = m0 + wm + mi*16 + g;
#pragma unroll
        for (int ni=0;ni<4;ni++) {
            int col = n0 + wn + ni*8 + tg*2;
            float2 v0 = {acc[mi][ni][0], acc[mi][ni][1]};
            float2 v1 = {acc[mi][ni][2], acc[mi][ni][3]};
            *(float2*)(Cb + (size_t)row*N + col) = v0;
            *(float2*)(Cb + (size_t)(row+8)*N + col) = v1;
        }
    }
}

// ------------------- persistent cluster GRU (round-11 layout) ---------------
// grid = (#slabs * 2 dirs) clusters of 8 CTAs; block = 256 threads.
// CTA owns (dir, 16-row slab, 32 units). W_hh slice staged to smem ONCE.
// thread: row = tid&15, up = tid>>4 (unit pair u0+2*up, u0+2*up+1)
__global__ void __cluster_dims__(CSZ, 1, 1) __launch_bounds__(256, 1)
k_gru_persist(const float* __restrict__ GI, float* __restrict__ HS,
              const float* __restrict__ whh, const float* __restrict__ bhh, int R)
{
    extern __shared__ float sm[];
    float* hbuf0 = sm;                         // [row*HPAD + k]
    float* hbuf1 = sm + RPS*HPAD;
    float2* wsm  = (float2*)(sm + 2*RPS*HPAD); // [(g*256+k)*16 + up]

    uint32_t rank;
    asm("mov.u32 %0, %%cluster_ctarank;" : "=r"(rank));
    int cid  = blockIdx.x >> 3;
    int dir  = cid & 1;
    int slab = cid >> 1;
    int r0   = slab * RPS;
    int u0   = (int)rank * UPC;

    int tid = threadIdx.x;
    int row = tid & 15;
    int up  = tid >> 4;
    int u   = u0 + up*2;

    for (int i = tid; i < 3*256*16; i += 256) {
        int g = i >> 12;
        int k = (i >> 4) & 255;
        int uu = i & 15;
        const float* wp = whh + ((size_t)(dir*768 + g*256 + u0 + uu*2))*256 + k;
        wsm[i] = make_float2(wp[0], wp[256]);
    }
    for (int i = tid; i < RPS*HPAD; i += 256) hbuf0[i] = 0.f;

    float br0 = bhh[dir*768 + u],        br1 = bhh[dir*768 + u + 1];
    float bz0 = bhh[dir*768 + 256 + u],  bz1 = bhh[dir*768 + 256 + u + 1];
    float bn0 = bhh[dir*768 + 512 + u],  bn1 = bhh[dir*768 + 512 + u + 1];

    uint32_t b0 = smem_u32(hbuf0), b1 = smem_u32(hbuf1);
    uint32_t p0[CSZ], p1[CSZ];
#pragma unroll
    for (int pr = 0; pr < CSZ; pr++) { p0[pr] = mapa_u32(b0, pr); p1[pr] = mapa_u32(b1, pr); }
    uint32_t xoff = (uint32_t)((row*HPAD + u) * 4);

    cluster_sync_();

    for (int s = 0; s < LSEQ; s++) {
        int t = dir ? (LSEQ-1-s) : s;
        const float* gip = GI + ((size_t)t*1536 + dir*768)*R + r0 + row;
        float gr0 = gip[(size_t)(u)      *R];
        float gr1 = gip[(size_t)(u+1)    *R];
        float gz0 = gip[(size_t)(256+u)  *R];
        float gz1 = gip[(size_t)(256+u+1)*R];
        float gn0 = gip[(size_t)(512+u)  *R];
        float gn1 = gip[(size_t)(512+u+1)*R];

        const float* hb = (s & 1) ? hbuf1 : hbuf0;
        const float* hrow = hb + row*HPAD;

        unsigned long long ar = 0, az = 0, an = 0;
#pragma unroll 8
        for (int k = 0; k < 256; k++) {
            unsigned long long h2 = pack2u(hrow[k]);
            ffma2u(ar, *(const unsigned long long*)&wsm[(       k)*16 + up], h2);
            ffma2u(az, *(const unsigned long long*)&wsm[( 256 + k)*16 + up], h2);
            ffma2u(an, *(const unsigned long long*)&wsm[( 512 + k)*16 + up], h2);
        }
        float2 AR = *(float2*)&ar, AZ = *(float2*)&az, AN = *(float2*)&an;
        float hp0 = hrow[u], hp1 = hrow[u+1];

        float rg0 = 1.f / (1.f + expf(-(gr0 + AR.x + br0)));
        float rg1 = 1.f / (1.f + expf(-(gr1 + AR.y + br1)));
        float zg0 = 1.f / (1.f + expf(-(gz0 + AZ.x + bz0)));
        float zg1 = 1.f / (1.f + expf(-(gz1 + AZ.y + bz1)));
        float ng0 = tanhf(gn0 + rg0 * (AN.x + bn0));
        float ng1 = tanhf(gn1 + rg1 * (AN.y + bn1));
        float h0 = (1.f - zg0) * ng0 + zg0 * hp0;
        float h1 = (1.f - zg1) * ng1 + zg1 * hp1;

        size_t hs = (((size_t)t*2 + dir)*HID + u)*R + r0 + row;
        HS[hs] = h0; HS[hs + R] = h1;

        float2 hv = make_float2(h0, h1);
        const uint32_t* pp = (s & 1) ? p0 : p1;
#pragma unroll
        for (int pr = 0; pr < CSZ; pr++) st_cluster64(pp[pr] + xoff, hv);

        cluster_sync_();
    }
}

// ------------------- transpose HS[t][d][u][r] -> OUT[r][t][d*256+u] ---------
__global__ void k_trans(const float* __restrict__ HS, float* __restrict__ OUT, int R)
{
    int t = blockIdx.x, dd0 = blockIdx.y*32, r0 = blockIdx.z*32;
    __shared__ float tile[32][33];
    int tx = threadIdx.x, ty = threadIdx.y;
#pragma unroll
    for (int i = 0; i < 4; i++) {
        int uu = ty + 8*i;
        int dd = dd0 + uu; int d = dd >> 8, u = dd & 255;
        tile[uu][tx] = HS[(((size_t)t*2 + d)*256 + u)*R + r0 + tx];
    }
    __syncthreads();
#pragma unroll
    for (int i = 0; i < 4; i++) {
        int rr = ty + 8*i;
        OUT[((size_t)(r0+rr)*LSEQ + t)*LD + dd0 + tx] = tile[tx][rr];
    }
}

// ------------------- BiDAF pre ----------------------------------------------
__global__ void k_bidaf_pre(const float* __restrict__ Cseq, const float* __restrict__ Qseq,
                            const float* __restrict__ bw,
                            float* __restrict__ CW, float* __restrict__ QW,
                            float* __restrict__ CW2, int cdiv)
{
    int r = blockIdx.y;
    int i = blockIdx.x*8 + (threadIdx.x >> 5);
    int lane = threadIdx.x & 31;
    const float* c = Cseq + ((size_t)(r >> cdiv)*LSEQ + i)*LD;
    const float* q = Qseq + ((size_t)r*LSEQ + i)*LD;
    float sc = 0.f, sq = 0.f;
    for (int d = lane; d < LD; d += 32) {
        float cv = c[d];
        sc = fmaf(cv, bw[d], sc);
        sq = fmaf(q[d], bw[512 + d], sq);
        CW2[((size_t)r*LSEQ + i)*LD + d] = cv * bw[1024 + d];
    }
#pragma unroll
    for (int o = 16; o; o >>= 1) {
        sc += __shfl_xor_sync(0xffffffffu, sc, o);
        sq += __shfl_xor_sync(0xffffffffu, sq, o);
    }
    if (!lane) { CW[r*LSEQ + i] = sc; QW[r*LSEQ + i] = sq; }
}

// ------------------- softmax over j, capture row max -------------------------
__global__ void k_softmax(float* __restrict__ S, const float* __restrict__ CW,
                          const float* __restrict__ QW, const float* __restrict__ bb,
                          float* __restrict__ Mx)
{
    int r = blockIdx.y, i = blockIdx.x, j = threadIdx.x;
    float bsum = bb[0] + bb[1] + bb[2];
    float* row = S + ((size_t)r*LSEQ + i)*LSEQ;
    float v = row[j] + CW[r*LSEQ + i] + QW[r*LSEQ + j] + bsum;
    __shared__ float red[16];
    float m = v;
#pragma unroll
    for (int o = 16; o; o >>= 1) m = fmaxf(m, __shfl_xor_sync(0xffffffffu, m, o));
    if (!(j & 31)) red[j >> 5] = m;
    __syncthreads();
    float mm = red[0];
#pragma unroll
    for (int w = 1; w < 8; w++) mm = fmaxf(mm, red[w]);
    float e = expf(v - mm);
    float s = e;
#pragma unroll
    for (int o = 16; o; o >>= 1) s += __shfl_xor_sync(0xffffffffu, s, o);
    __syncthreads();
    if (!(j & 31)) red[8 + (j >> 5)] = s;
    __syncthreads();
    float ss = 0.f;
#pragma unroll
    for (int w = 0; w < 8; w++) ss += red[8 + w];
    row[j] = e / ss;
    if (j == 0) Mx[r*LSEQ + i] = mm;
}

// ------------------- q2c ------------------------------------------------------
__global__ void k_q2c(const float* __restrict__ Mx, const float* __restrict__ Cseq,
                      float* __restrict__ Q2C, int cdiv)
{
    int r = blockIdx.x, tid = threadIdx.x;
    __shared__ float red[8];
    __shared__ float bbv[256];
    float m = Mx[r*LSEQ + tid];
    float w = m;
#pragma unroll
    for (int o = 16; o; o >>= 1) w = fmaxf(w, __shfl_xor_sync(0xffffffffu, w, o));
    if (!(tid & 31)) red[tid >> 5] = w;
    __syncthreads();
    float mm = red[0];
#pragma unroll
    for (int i = 1; i < 8; i++) mm = fmaxf(mm, red[i]);
    float e = expf(m - mm);
    bbv[tid] = e;
    float s = e;
#pragma unroll
    for (int o = 16; o; o >>= 1) s += __shfl_xor_sync(0xffffffffu, s, o);
    __syncthreads();
    if (!(tid & 31)) red[tid >> 5] = s;
    __syncthreads();
    float ss = 0.f;
#pragma unroll
    for (int i = 0; i < 8; i++) ss += red[i];
    float inv = 1.f / ss;
    const float* cb = Cseq + (size_t)(r >> cdiv)*LSEQ*LD;
    for (int d = tid; d < LD; d += 256) {
        float acc = 0.f;
        for (int i = 0; i < 256; i++) acc = fmaf(bbv[i], cb[(size_t)i*LD + d], acc);
        Q2C[r*LD + d] = acc * inv;
    }
}

// ------------------- attention output assembly + relu ------------------------
__global__ void k_att(const float* __restrict__ Cseq, const float* __restrict__ C2Q,
                      const float* __restrict__ Q2C, float* __restrict__ ATT, int cdiv)
{
    int i = blockIdx.x, r = blockIdx.y, d = threadIdx.x;
    float cv  = Cseq[((size_t)(r >> cdiv)*LSEQ + i)*LD + d];
    float c2q = C2Q [((size_t)r*LSEQ + i)*LD + d];
    float q2c = Q2C [r*LD + d];
    float* o = ATT + ((size_t)i*NR2 + r)*F8;
    o[d]        = fmaxf(cv, 0.f);
    o[512 + d]  = fmaxf(c2q, 0.f);
    o[1024 + d] = fmaxf(cv * c2q, 0.f);
    o[1536 + d] = fmaxf(cv * q2c, 0.f);
}

// ------------------- final: max over k, dot rank_w (2-phase) ------------------
__global__ void k_final1(const float* __restrict__ A1, const float* __restrict__ A2,
                         const float* __restrict__ rw, float* __restrict__ part)
{
    int bo = blockIdx.x, tile = blockIdx.y, tid = threadIdx.x;
    int r0 = bo*2, r1 = r0 + 1;
    float acc = 0.f;
    for (int ii = 0; ii < 16; ii++) {
        int i = tile*16 + ii;
        size_t base0 = ((size_t)i*NR2 + r0)*F8;
        size_t base1 = ((size_t)i*NR2 + r1)*F8;
        const float4* a0 = (const float4*)(A1 + base0);
        const float4* a1 = (const float4*)(A1 + base1);
        const float4* b0 = (const float4*)(A2 + base0);
        const float4* b1 = (const float4*)(A2 + base1);
        const float4* w  = (const float4*)(rw + (size_t)i*F8);
#pragma unroll
        for (int f = tid; f < 512; f += 256) {
            float4 x0 = a0[f], x1 = a1[f], y0 = b0[f], y1 = b1[f], wv = w[f];
            acc = fmaf(wv.x, fmaxf(x0.x + y0.x, x1.x + y1.x), acc);
            acc = fmaf(wv.y, fmaxf(x0.y + y0.y, x1.y + y1.y), acc);
            acc = fmaf(wv.z, fmaxf(x0.z + y0.z, x1.z + y1.z), acc);
            acc = fmaf(wv.w, fmaxf(x0.w + y0.w, x1.w + y1.w), acc);
        }
    }
    __shared__ float red[8];
#pragma unroll
    for (int o = 16; o; o >>= 1) acc += __shfl_xor_sync(0xffffffffu, acc, o);
    if (!(tid & 31)) red[tid >> 5] = acc;
    __syncthreads();
    if (tid == 0) {
        float s = 0.f;
        for (int i = 0; i < 8; i++) s += red[i];
        part[bo*16 + tile] = s;
    }
}

__global__ void k_final2(const float* __restrict__ part, const float* __restrict__ rb,
                         float* __restrict__ out)
{
    int bo = threadIdx.x;
    float s = 0.f;
    for (int t = 0; t < 16; t++) s += part[bo*16 + t];
    out[bo] = s + rb[0];
}

// ------------------- host driver ---------------------------------------------
extern "C" void kernel_launch(void* const* d_in, const int* in_sizes, int n_in,
                              void* d_out, int out_size)
{
    const int*   q     = (const int*)d_in[0];
    const int*   a     = (const int*)d_in[1];
    const float* emb   = (const float*)d_in[2];
    const float* g1_wih = (const float*)d_in[3];
    const float* g1_whh = (const float*)d_in[4];
    const float* g1_bih = (const float*)d_in[5];
    const float* g1_bhh = (const float*)d_in[6];
    const float* g2_wih = (const float*)d_in[7];
    const float* g2_whh = (const float*)d_in[8];
    const float* g2_bih = (const float*)d_in[9];
    const float* g2_bhh = (const float*)d_in[10];
    const float* b1_w  = (const float*)d_in[11];
    const float* b1_b  = (const float*)d_in[12];
    const float* b2_w  = (const float*)d_in[13];
    const float* b2_b  = (const float*)d_in[14];
    const float* rank_w = (const float*)d_in[15];
    const float* rank_b = (const float*)d_in[16];
    float* out = (float*)d_out;

    float *X1, *GI1, *HS1, *CQ1, *CW2, *S, *CW, *QW, *Mx, *Q2C, *C2Q, *ATT, *GI2, *HS2, *C2, *AT2, *PART;
    cudaGetSymbolAddress((void**)&X1,  g_X1);
    cudaGetSymbolAddress((void**)&GI1, g_GI1);
    cudaGetSymbolAddress((void**)&HS1, g_HS1);
    cudaGetSymbolAddress((void**)&CQ1, g_CQ1);
    cudaGetSymbolAddress((void**)&CW2, g_CW2);
    cudaGetSymbolAddress((void**)&S,   g_S);
    cudaGetSymbolAddress((void**)&CW,  g_CW);
    cudaGetSymbolAddress((void**)&QW,  g_QW);
    cudaGetSymbolAddress((void**)&Mx,  g_M);
    cudaGetSymbolAddress((void**)&Q2C, g_Q2C);
    cudaGetSymbolAddress((void**)&C2Q, g_C2Q);
    cudaGetSymbolAddress((void**)&ATT, g_ATT);
    cudaGetSymbolAddress((void**)&GI2, g_GI2);
    cudaGetSymbolAddress((void**)&HS2, g_HS2);
    cudaGetSymbolAddress((void**)&C2,  g_C2);
    cudaGetSymbolAddress((void**)&AT2, g_AT2);
    cudaGetSymbolAddress((void**)&PART, g_PART);

    const int GSMEM = (2*128*36 + 2*64*36) * 4;     // 55296 B (NT and NN equal)
    const int PSMEM = (2*RPS*HPAD)*4 + 3*256*16*8;  // 131328 B
    cudaFuncSetAttribute(k_tc_nt, cudaFuncAttributeMaxDynamicSharedMemorySize, GSMEM);
    cudaFuncSetAttribute(k_tc_nn, cudaFuncAttributeMaxDynamicSharedMemorySize, GSMEM);
    cudaFuncSetAttribute(k_gru_persist, cudaFuncAttributeMaxDynamicSharedMemorySize, PSMEM);

    // 1) embedding
    k_embed<<<dim3(LSEQ, NR1), 64>>>(q, a, emb);

    // 2) GI1 = Wih1 @ X1[t]^T (tf32 TC, batched over t)
    k_tc_nt<<<dim3(12, 2, LSEQ), 256, GSMEM>>>(g1_wih, X1, GI1, g1_bih,
                                        1536, NR1, VEC, 0, (long)NR1*VEC, (long)1536*NR1);
    // 3) BiGRU-1: persistent cluster kernel
    k_gru_persist<<<96, 256, PSMEM>>>(GI1, HS1, g1_whh, g1_bhh, NR1);
    // 4) transpose to [seq][t][d]
    k_trans<<<dim3(LSEQ, 16, NR1/32), dim3(32, 8)>>>(HS1, CQ1, NR1);

    // 5) BiDAF-1 (c = question enc, q = article enc)
    const float* Qb1 = CQ1 + (size_t)32*LSEQ*LD;
    k_bidaf_pre<<<dim3(32, NR2), 256>>>(CQ1, Qb1, b1_w, CW, QW, CW2, 1);
    k_tc_nt<<<dim3(2, 4, NR2), 256, GSMEM>>>(CW2, Qb1, S, nullptr,
                                      256, 256, 512, (long)LSEQ*LD, (long)LSEQ*LD, (long)LSEQ*LSEQ);
    k_softmax<<<dim3(LSEQ, NR2), 256>>>(S, CW, QW, b1_b, Mx);
    k_q2c<<<NR2, 256>>>(Mx, CQ1, Q2C, 1);
    k_tc_nn<<<dim3(2, 8, NR2), 256, GSMEM>>>(S, Qb1, C2Q,
                                      256, 512, 256, (long)LSEQ*LSEQ, (long)LSEQ*LD, (long)LSEQ*LD);
    k_att<<<dim3(LSEQ, NR2), 512>>>(CQ1, C2Q, Q2C, ATT, 1);

    // 6) GI2 = Wih2 @ ATT[t]^T (tf32 TC, batched over t)
    k_tc_nt<<<dim3(12, 1, LSEQ), 256, GSMEM>>>(g2_wih, ATT, GI2, g2_bih,
                                        1536, NR2, F8, 0, (long)NR2*F8, (long)1536*NR2);
    // 7) BiGRU-2
    k_gru_persist<<<64, 256, PSMEM>>>(GI2, HS2, g2_whh, g2_bhh, NR2);
    k_trans<<<dim3(LSEQ, 16, NR2/32), dim3(32, 8)>>>(HS2, C2, NR2);

    // 8) BiDAF-2 (self)
    k_bidaf_pre<<<dim3(32, NR2), 256>>>(C2, C2, b2_w, CW, QW, CW2, 0);
    k_tc_nt<<<dim3(2, 4, NR2), 256, GSMEM>>>(CW2, C2, S, nullptr,
                                      256, 256, 512, (long)LSEQ*LD, (long)LSEQ*LD, (long)LSEQ*LSEQ);
    k_softmax<<<dim3(LSEQ, NR2), 256>>>(S, CW, QW, b2_b, Mx);
    k_q2c<<<NR2, 256>>>(Mx, C2, Q2C, 0);
    k_tc_nn<<<dim3(2, 8, NR2), 256, GSMEM>>>(S, C2, C2Q,
                                      256, 512, 256, (long)LSEQ*LSEQ, (long)LSEQ*LD, (long)LSEQ*LD);
    k_att<<<dim3(LSEQ, NR2), 512>>>(C2, C2Q, Q2C, AT2, 0);

    // 9) final
    k_final1<<<dim3(32, 16), 256>>>(ATT, AT2, rank_w, PART);
    k_final2<<<1, 32>>>(PART, rank_b, out);
}

// round 16
// speedup vs baseline: 1.0019x; 1.0019x over previous
#include <cuda_runtime.h>
#include <math.h>
#include <stdint.h>

#define LSEQ 256
#define VEC  256
#define HID  256
#define NR1  96      // 32 question seqs + 64 article seqs
#define NR2  64      // Beff rows
#define LD   512     // 2*HID
#define F8   2048

#define RPS   16     // rows per slab (per cluster)
#define UPC   32     // units per CTA
#define CSZ   8      // cluster size
#define HPAD  258    // padded row stride (floats) in h buffer

// ------------------- scratch (device globals; no allocs) -------------------
__device__ __align__(256) float g_X1 [LSEQ*NR1*VEC];
__device__ __align__(256) float g_GI1[LSEQ*1536*NR1];
__device__ __align__(256) float g_HS1[LSEQ*2*HID*NR1];
__device__ __align__(256) float g_CQ1[NR1*LSEQ*LD];
__device__ __align__(256) float g_CW2[NR2*LSEQ*LD];
__device__ __align__(256) float g_S  [NR2*LSEQ*LSEQ];
__device__ __align__(256) float g_CW [NR2*LSEQ];
__device__ __align__(256) float g_QW [NR2*LSEQ];
__device__ __align__(256) float g_M  [NR2*LSEQ];
__device__ __align__(256) float g_Q2C[NR2*LD];
__device__ __align__(256) float g_C2Q[NR2*LSEQ*LD];
__device__ __align__(256) float g_ATT[LSEQ*NR2*F8];
__device__ __align__(256) float g_GI2[LSEQ*1536*NR2];
__device__ __align__(256) float g_HS2[LSEQ*2*HID*NR2];
__device__ __align__(256) float g_C2 [NR2*LSEQ*LD];
__device__ __align__(256) float g_AT2[LSEQ*NR2*F8];
__device__ __align__(256) float g_PART[32*16];

// ------------------- packed fp32x2 helpers ---------------------------------
__device__ __forceinline__ void ffma2u(unsigned long long& acc,
                                       unsigned long long a, unsigned long long b) {
    asm("fma.rn.f32x2 %0, %1, %2, %0;" : "+l"(acc) : "l"(a), "l"(b));
}
__device__ __forceinline__ unsigned long long pack2u(float w) {
    unsigned long long r;
    asm("mov.b64 %0, {%1, %1};" : "=l"(r) : "f"(w));
    return r;
}

// ------------------- tf32 tensor-core helpers --------------------------------
__device__ __forceinline__ uint32_t f2tf32(float x) {
    uint32_t r; asm("cvt.rna.tf32.f32 %0, %1;" : "=r"(r) : "f"(x)); return r;
}
__device__ __forceinline__ void mma_tf32(float* c, const uint32_t* a,
                                         uint32_t b0, uint32_t b1) {
    asm volatile("mma.sync.aligned.m16n8k8.row.col.f32.tf32.tf32.f32 "
        "{%0,%1,%2,%3}, {%4,%5,%6,%7}, {%8,%9}, {%0,%1,%2,%3};"
        : "+f"(c[0]), "+f"(c[1]), "+f"(c[2]), "+f"(c[3])
        : "r"(a[0]), "r"(a[1]), "r"(a[2]), "r"(a[3]), "r"(b0), "r"(b1));
}

// ------------------- cluster helpers ----------------------------------------
__device__ __forceinline__ uint32_t smem_u32(const void* p) {
    return (uint32_t)__cvta_generic_to_shared(p);
}
__device__ __forceinline__ uint32_t mapa_u32(uint32_t addr, uint32_t rank) {
    uint32_t r;
    asm("mapa.shared::cluster.u32 %0, %1, %2;" : "=r"(r) : "r"(addr), "r"(rank));
    return r;
}
__device__ __forceinline__ void st_cluster64(uint32_t addr, float2 v) {
    asm volatile("st.shared::cluster.b64 [%0], %1;"
                 :: "r"(addr), "l"(*(unsigned long long*)&v) : "memory");
}
__device__ __forceinline__ void cluster_sync_() {
    asm volatile("barrier.cluster.arrive.aligned;" ::: "memory");
    asm volatile("barrier.cluster.wait.aligned;" ::: "memory");
}

// ------------------- embedding gather ---------------------------------------
__global__ void k_embed(const int* __restrict__ q, const int* __restrict__ a,
                        const float* __restrict__ emb)
{
    int t = blockIdx.x, r = blockIdx.y;
    int tok = (r < 32) ? q[r*LSEQ + t] : a[(r-32)*LSEQ + t];
    const float4* src = (const float4*)(emb + (size_t)tok*VEC);
    float4* dst = (float4*)(g_X1 + ((size_t)t*NR1 + r)*VEC);
    dst[threadIdx.x] = src[threadIdx.x];
}

// ------------------- tf32 TC GEMM NT (double-buffered, 1 sync/iter) ---------
// BM=128, BN=64, BK=32, 256 threads = 8 warps (4m x 2n), warp tile 32x32.
// M%128==0, K%32==0; N guarded (even N).
__global__ __launch_bounds__(256) void k_tc_nt(
    const float* __restrict__ A, const float* __restrict__ B,
    float* __restrict__ C, const float* __restrict__ bias,
    int M, int N, int K, long sA, long sB, long sC)
{
    extern __shared__ uint32_t gsm[];
    uint32_t (*As)[36] = (uint32_t(*)[36])gsm;              // [2*128][36]
    uint32_t (*Bs)[36] = (uint32_t(*)[36])(gsm + 2*128*36); // [2*64][36]
    const float* Ab = A + (size_t)blockIdx.z * sA;
    const float* Bb = B + (size_t)blockIdx.z * sB;
    float* Cb = C + (size_t)blockIdx.z * sC;
    int m0 = blockIdx.x*128, n0 = blockIdx.y*64;
    int tid = threadIdx.x, lane = tid & 31;
    int wm = ((tid>>5) & 3)*32, wn = (tid>>7)*32;
    int g = lane>>2, tg = lane&3;
    int am = tid>>3, ac = tid&7;

    float4 ra[4], rb[2];
    float acc[2][4][4];
#pragma unroll
    for (int i=0;i<2;i++)
#pragma unroll
        for (int j=0;j<4;j++)
#pragma unroll
            for (int l=0;l<4;l++) acc[i][j][l]=0.f;

    auto LDG = [&](int k0) {
#pragma unroll
        for (int p=0;p<4;p++)
            ra[p] = *(const float4*)(Ab + (size_t)(m0+am+32*p)*K + k0 + ac*4);
#pragma unroll
        for (int p=0;p<2;p++) {
            int n = n0 + am + 32*p;
            rb[p] = (n < N) ? *(const float4*)(Bb + (size_t)n*K + k0 + ac*4)
                            : make_float4(0.f,0.f,0.f,0.f);
        }
    };
    auto STS = [&](int b) {
#pragma unroll
        for (int p=0;p<4;p++) {
            uint4 v = {f2tf32(ra[p].x),f2tf32(ra[p].y),f2tf32(ra[p].z),f2tf32(ra[p].w)};
            *(uint4*)&As[b*128 + am+32*p][ac*4] = v;
        }
#pragma unroll
        for (int p=0;p<2;p++) {
            uint4 v = {f2tf32(rb[p].x),f2tf32(rb[p].y),f2tf32(rb[p].z),f2tf32(rb[p].w)};
            *(uint4*)&Bs[b*64 + am+32*p][ac*4] = v;
        }
    };
    auto COMPUTE = [&](int b) {
#pragma unroll
        for (int ks=0;ks<4;ks++) {
            uint32_t a[2][4];
#pragma unroll
            for (int mi=0;mi<2;mi++) {
                int r = b*128 + wm + mi*16 + g, c = ks*8 + tg;
                a[mi][0]=As[r][c];   a[mi][1]=As[r+8][c];
                a[mi][2]=As[r][c+4]; a[mi][3]=As[r+8][c+4];
            }
#pragma unroll
            for (int ni=0;ni<4;ni++) {
                int bn = b*64 + wn + ni*8 + g, bk = ks*8 + tg;
                uint32_t b0=Bs[bn][bk], b1=Bs[bn][bk+4];
                mma_tf32(acc[0][ni], a[0], b0, b1);
                mma_tf32(acc[1][ni], a[1], b0, b1);
            }
        }
    };

    LDG(0); STS(0); __syncthreads();
    int cur = 0;
    for (int k0 = 32; k0 < K; k0 += 32) {
        LDG(k0);
        COMPUTE(cur);
        STS(cur^1);
        __syncthreads();
        cur ^= 1;
    }
    COMPUTE(cur);

#pragma unroll
    for (int mi=0;mi<2;mi++) {
        int row = m0 + wm + mi*16 + g;
        float b0v = bias ? bias[row]   : 0.f;
        float b8v = bias ? bias[row+8] : 0.f;
#pragma unroll
        for (int ni=0;ni<4;ni++) {
            int col = n0 + wn + ni*8 + tg*2;
            if (col < N) {
                float2 v0 = {acc[mi][ni][0] + b0v, acc[mi][ni][1] + b0v};
                float2 v1 = {acc[mi][ni][2] + b8v, acc[mi][ni][3] + b8v};
                *(float2*)(Cb + (size_t)row*N + col) = v0;
                *(float2*)(Cb + (size_t)(row+8)*N + col) = v1;
            }
        }
    }
}

// ------------------- tf32 TC GEMM NN (double-buffered, 1 sync/iter) ---------
// BM=128, BN=64, BK=32. M%128==0, N%64==0, K%32==0.
__global__ __launch_bounds__(256) void k_tc_nn(
    const float* __restrict__ A, const float* __restrict__ B,
    float* __restrict__ C,
    int M, int N, int K, long sA, long sB, long sC)
{
    extern __shared__ uint32_t gsm[];
    uint32_t (*As)[36] = (uint32_t(*)[36])gsm;              // [2*128][36]
    uint32_t (*Bs)[72] = (uint32_t(*)[72])(gsm + 2*128*36); // [2*32][72]
    const float* Ab = A + (size_t)blockIdx.z * sA;
    const float* Bb = B + (size_t)blockIdx.z * sB;
    float* Cb = C + (size_t)blockIdx.z * sC;
    int m0 = blockIdx.x*128, n0 = blockIdx.y*64;
    int tid = threadIdx.x, lane = tid & 31;
    int wm = ((tid>>5) & 3)*32, wn = (tid>>7)*32;
    int g = lane>>2, tg = lane&3;
    int am = tid>>3, ac = tid&7;
    int bk = tid>>4, bc = tid&15;

    float4 ra[4], rb[2];
    float acc[2][4][4];
#pragma unroll
    for (int i=0;i<2;i++)
#pragma unroll
        for (int j=0;j<4;j++)
#pragma unroll
            for (int l=0;l<4;l++) acc[i][j][l]=0.f;

    auto LDG = [&](int k0) {
#pragma unroll
        for (int p=0;p<4;p++)
            ra[p] = *(const float4*)(Ab + (size_t)(m0+am+32*p)*K + k0 + ac*4);
#pragma unroll
        for (int p=0;p<2;p++)
            rb[p] = *(const float4*)(Bb + (size_t)(k0+bk+16*p)*N + n0 + bc*4);
    };
    auto STS = [&](int b) {
#pragma unroll
        for (int p=0;p<4;p++) {
            uint4 v = {f2tf32(ra[p].x),f2tf32(ra[p].y),f2tf32(ra[p].z),f2tf32(ra[p].w)};
            *(uint4*)&As[b*128 + am+32*p][ac*4] = v;
        }
#pragma unroll
        for (int p=0;p<2;p++) {
            uint4 v = {f2tf32(rb[p].x),f2tf32(rb[p].y),f2tf32(rb[p].z),f2tf32(rb[p].w)};
            *(uint4*)&Bs[b*32 + bk+16*p][bc*4] = v;
        }
    };
    auto COMPUTE = [&](int b) {
#pragma unroll
        for (int ks=0;ks<4;ks++) {
            uint32_t a[2][4];
#pragma unroll
            for (int mi=0;mi<2;mi++) {
                int r = b*128 + wm + mi*16 + g, c = ks*8 + tg;
                a[mi][0]=As[r][c];   a[mi][1]=As[r+8][c];
                a[mi][2]=As[r][c+4]; a[mi][3]=As[r+8][c+4];
            }
#pragma unroll
            for (int ni=0;ni<4;ni++) {
                int bn = wn + ni*8 + g;
                uint32_t b0=Bs[b*32 + ks*8+tg][bn], b1=Bs[b*32 + ks*8+tg+4][bn];
                mma_tf32(acc[0][ni], a[0], b0, b1);
                mma_tf32(acc[1][ni], a[1], b0, b1);
            }
        }
    };

    LDG(0); STS(0); __syncthreads();
    int cur = 0;
    for (int k0 = 32; k0 < K; k0 += 32) {
        LDG(k0);
        COMPUTE(cur);
        STS(cur^1);
        __syncthreads();
        cur ^= 1;
    }
    COMPUTE(cur);

#pragma unroll
    for (int mi=0;mi<2;mi++) {
        int row = m0 + wm + mi*16 + g;
#pragma unroll
        for (int ni=0;ni<4;ni++) {
            int col = n0 + wn + ni*8 + tg*2;
            float2 v0 = {acc[mi][ni][0], acc[mi][ni][1]};
            float2 v1 = {acc[mi][ni][2], acc[mi][ni][3]};
            *(float2*)(Cb + (size_t)row*N + col) = v0;
            *(float2*)(Cb + (size_t)(row+8)*N + col) = v1;
        }
    }
}

// ------------------- persistent cluster GRU (round-11 layout) ---------------
// grid = (#slabs * 2 dirs) clusters of 8 CTAs; block = 256 threads.
// CTA owns (dir, 16-row slab, 32 units). W_hh slice staged to smem ONCE.
// thread: row = tid&15, up = tid>>4 (unit pair u0+2*up, u0+2*up+1)
__global__ void __cluster_dims__(CSZ, 1, 1) __launch_bounds__(256, 1)
k_gru_persist(const float* __restrict__ GI, float* __restrict__ HS,
              const float* __restrict__ whh, const float* __restrict__ bhh, int R)
{
    extern __shared__ float sm[];
    float* hbuf0 = sm;                         // [row*HPAD + k]
    float* hbuf1 = sm + RPS*HPAD;
    float2* wsm  = (float2*)(sm + 2*RPS*HPAD); // [(g*256+k)*16 + up]

    uint32_t rank;
    asm("mov.u32 %0, %%cluster_ctarank;" : "=r"(rank));
    int cid  = blockIdx.x >> 3;
    int dir  = cid & 1;
    int slab = cid >> 1;
    int r0   = slab * RPS;
    int u0   = (int)rank * UPC;

    int tid = threadIdx.x;
    int row = tid & 15;
    int up  = tid >> 4;
    int u   = u0 + up*2;

    for (int i = tid; i < 3*256*16; i += 256) {
        int g = i >> 12;
        int k = (i >> 4) & 255;
        int uu = i & 15;
        const float* wp = whh + ((size_t)(dir*768 + g*256 + u0 + uu*2))*256 + k;
        wsm[i] = make_float2(wp[0], wp[256]);
    }
    for (int i = tid; i < RPS*HPAD; i += 256) hbuf0[i] = 0.f;

    float br0 = bhh[dir*768 + u],        br1 = bhh[dir*768 + u + 1];
    float bz0 = bhh[dir*768 + 256 + u],  bz1 = bhh[dir*768 + 256 + u + 1];
    float bn0 = bhh[dir*768 + 512 + u],  bn1 = bhh[dir*768 + 512 + u + 1];

    uint32_t b0 = smem_u32(hbuf0), b1 = smem_u32(hbuf1);
    uint32_t p0[CSZ], p1[CSZ];
#pragma unroll
    for (int pr = 0; pr < CSZ; pr++) { p0[pr] = mapa_u32(b0, pr); p1[pr] = mapa_u32(b1, pr); }
    uint32_t xoff = (uint32_t)((row*HPAD + u) * 4);

    cluster_sync_();

    for (int s = 0; s < LSEQ; s++) {
        int t = dir ? (LSEQ-1-s) : s;
        const float* gip = GI + ((size_t)t*1536 + dir*768)*R + r0 + row;
        float gr0 = gip[(size_t)(u)      *R];
        float gr1 = gip[(size_t)(u+1)    *R];
        float gz0 = gip[(size_t)(256+u)  *R];
        float gz1 = gip[(size_t)(256+u+1)*R];
        float gn0 = gip[(size_t)(512+u)  *R];
        float gn1 = gip[(size_t)(512+u+1)*R];

        const float* hb = (s & 1) ? hbuf1 : hbuf0;
        const float* hrow = hb + row*HPAD;

        unsigned long long ar = 0, az = 0, an = 0;
#pragma unroll 8
        for (int k = 0; k < 256; k++) {
            unsigned long long h2 = pack2u(hrow[k]);
            ffma2u(ar, *(const unsigned long long*)&wsm[(       k)*16 + up], h2);
            ffma2u(az, *(const unsigned long long*)&wsm[( 256 + k)*16 + up], h2);
            ffma2u(an, *(const unsigned long long*)&wsm[( 512 + k)*16 + up], h2);
        }
        float2 AR = *(float2*)&ar, AZ = *(float2*)&az, AN = *(float2*)&an;
        float hp0 = hrow[u], hp1 = hrow[u+1];

        float rg0 = 1.f / (1.f + expf(-(gr0 + AR.x + br0)));
        float rg1 = 1.f / (1.f + expf(-(gr1 + AR.y + br1)));
        float zg0 = 1.f / (1.f + expf(-(gz0 + AZ.x + bz0)));
        float zg1 = 1.f / (1.f + expf(-(gz1 + AZ.y + bz1)));
        float ng0 = tanhf(gn0 + rg0 * (AN.x + bn0));
        float ng1 = tanhf(gn1 + rg1 * (AN.y + bn1));
        float h0 = (1.f - zg0) * ng0 + zg0 * hp0;
        float h1 = (1.f - zg1) * ng1 + zg1 * hp1;

        size_t hs = (((size_t)t*2 + dir)*HID + u)*R + r0 + row;
        HS[hs] = h0; HS[hs + R] = h1;

        float2 hv = make_float2(h0, h1);
        const uint32_t* pp = (s & 1) ? p0 : p1;
#pragma unroll
        for (int pr = 0; pr < CSZ; pr++) st_cluster64(pp[pr] + xoff, hv);

        cluster_sync_();
    }
}

// ------------------- transpose HS[t][d][u][r] -> OUT[r][t][d*256+u] ---------
__global__ void k_trans(const float* __restrict__ HS, float* __restrict__ OUT, int R)
{
    int t = blockIdx.x, dd0 = blockIdx.y*32, r0 = blockIdx.z*32;
    __shared__ float tile[32][33];
    int tx = threadIdx.x, ty = threadIdx.y;
#pragma unroll
    for (int i = 0; i < 4; i++) {
        int uu = ty + 8*i;
        int dd = dd0 + uu; int d = dd >> 8, u = dd & 255;
        tile[uu][tx] = HS[(((size_t)t*2 + d)*256 + u)*R + r0 + tx];
    }
    __syncthreads();
#pragma unroll
    for (int i = 0; i < 4; i++) {
        int rr = ty + 8*i;
        OUT[((size_t)(r0+rr)*LSEQ + t)*LD + dd0 + tx] = tile[tx][rr];
    }
}

// ------------------- BiDAF pre ----------------------------------------------
__global__ void k_bidaf_pre(const float* __restrict__ Cseq, const float* __restrict__ Qseq,
                            const float* __restrict__ bw,
                            float* __restrict__ CW, float* __restrict__ QW,
                            float* __restrict__ CW2, int cdiv)
{
    int r = blockIdx.y;
    int i = blockIdx.x*8 + (threadIdx.x >> 5);
    int lane = threadIdx.x & 31;
    const float* c = Cseq + ((size_t)(r >> cdiv)*LSEQ + i)*LD;
    const float* q = Qseq + ((size_t)r*LSEQ + i)*LD;
    float sc = 0.f, sq = 0.f;
    for (int d = lane; d < LD; d += 32) {
        float cv = c[d];
        sc = fmaf(cv, bw[d], sc);
        sq = fmaf(q[d], bw[512 + d], sq);
        CW2[((size_t)r*LSEQ + i)*LD + d] = cv * bw[1024 + d];
    }
#pragma unroll
    for (int o = 16; o; o >>= 1) {
        sc += __shfl_xor_sync(0xffffffffu, sc, o);
        sq += __shfl_xor_sync(0xffffffffu, sq, o);
    }
    if (!lane) { CW[r*LSEQ + i] = sc; QW[r*LSEQ + i] = sq; }
}

// ------------------- softmax over j, capture row max -------------------------
__global__ void k_softmax(float* __restrict__ S, const float* __restrict__ CW,
                          const float* __restrict__ QW, const float* __restrict__ bb,
                          float* __restrict__ Mx)
{
    int r = blockIdx.y, i = blockIdx.x, j = threadIdx.x;
    float bsum = bb[0] + bb[1] + bb[2];
    float* row = S + ((size_t)r*LSEQ + i)*LSEQ;
    float v = row[j] + CW[r*LSEQ + i] + QW[r*LSEQ + j] + bsum;
    __shared__ float red[16];
    float m = v;
#pragma unroll
    for (int o = 16; o; o >>= 1) m = fmaxf(m, __shfl_xor_sync(0xffffffffu, m, o));
    if (!(j & 31)) red[j >> 5] = m;
    __syncthreads();
    float mm = red[0];
#pragma unroll
    for (int w = 1; w < 8; w++) mm = fmaxf(mm, red[w]);
    float e = expf(v - mm);
    float s = e;
#pragma unroll
    for (int o = 16; o; o >>= 1) s += __shfl_xor_sync(0xffffffffu, s, o);
    __syncthreads();
    if (!(j & 31)) red[8 + (j >> 5)] = s;
    __syncthreads();
    float ss = 0.f;
#pragma unroll
    for (int w = 0; w < 8; w++) ss += red[8 + w];
    row[j] = e / ss;
    if (j == 0) Mx[r*LSEQ + i] = mm;
}

// ------------------- q2c ------------------------------------------------------
__global__ void k_q2c(const float* __restrict__ Mx, const float* __restrict__ Cseq,
                      float* __restrict__ Q2C, int cdiv)
{
    int r = blockIdx.x, tid = threadIdx.x;
    __shared__ float red[8];
    __shared__ float bbv[256];
    float m = Mx[r*LSEQ + tid];
    float w = m;
#pragma unroll
    for (int o = 16; o; o >>= 1) w = fmaxf(w, __shfl_xor_sync(0xffffffffu, w, o));
    if (!(tid & 31)) red[tid >> 5] = w;
    __syncthreads();
    float mm = red[0];
#pragma unroll
    for (int i = 1; i < 8; i++) mm = fmaxf(mm, red[i]);
    float e = expf(m - mm);
    bbv[tid] = e;
    float s = e;
#pragma unroll
    for (int o = 16; o; o >>= 1) s += __shfl_xor_sync(0xffffffffu, s, o);
    __syncthreads();
    if (!(tid & 31)) red[tid >> 5] = s;
    __syncthreads();
    float ss = 0.f;
#pragma unroll
    for (int i = 0; i < 8; i++) ss += red[i];
    float inv = 1.f / ss;
    const float* cb = Cseq + (size_t)(r >> cdiv)*LSEQ*LD;
    for (int d = tid; d < LD; d += 256) {
        float acc = 0.f;
        for (int i = 0; i < 256; i++) acc = fmaf(bbv[i], cb[(size_t)i*LD + d], acc);
        Q2C[r*LD + d] = acc * inv;
    }
}

// ------------------- attention output assembly + relu ------------------------
__global__ void k_att(const float* __restrict__ Cseq, const float* __restrict__ C2Q,
                      const float* __restrict__ Q2C, float* __restrict__ ATT, int cdiv)
{
    int i = blockIdx.x, r = blockIdx.y, d = threadIdx.x;
    float cv  = Cseq[((size_t)(r >> cdiv)*LSEQ + i)*LD + d];
    float c2q = C2Q [((size_t)r*LSEQ + i)*LD + d];
    float q2c = Q2C [r*LD + d];
    float* o = ATT + ((size_t)i*NR2 + r)*F8;
    o[d]        = fmaxf(cv, 0.f);
    o[512 + d]  = fmaxf(c2q, 0.f);
    o[1024 + d] = fmaxf(cv * c2q, 0.f);
    o[1536 + d] = fmaxf(cv * q2c, 0.f);
}

// ------------------- final: max over k, dot rank_w (2-phase) ------------------
__global__ void k_final1(const float* __restrict__ A1, const float* __restrict__ A2,
                         const float* __restrict__ rw, float* __restrict__ part)
{
    int bo = blockIdx.x, tile = blockIdx.y, tid = threadIdx.x;
    int r0 = bo*2, r1 = r0 + 1;
    float acc = 0.f;
    for (int ii = 0; ii < 16; ii++) {
        int i = tile*16 + ii;
        size_t base0 = ((size_t)i*NR2 + r0)*F8;
        size_t base1 = ((size_t)i*NR2 + r1)*F8;
        const float4* a0 = (const float4*)(A1 + base0);
        const float4* a1 = (const float4*)(A1 + base1);
        const float4* b0 = (const float4*)(A2 + base0);
        const float4* b1 = (const float4*)(A2 + base1);
        const float4* w  = (const float4*)(rw + (size_t)i*F8);
#pragma unroll
        for (int f = tid; f < 512; f += 256) {
            float4 x0 = a0[f], x1 = a1[f], y0 = b0[f], y1 = b1[f], wv = w[f];
            acc = fmaf(wv.x, fmaxf(x0.x + y0.x, x1.x + y1.x), acc);
            acc = fmaf(wv.y, fmaxf(x0.y + y0.y, x1.y + y1.y), acc);
            acc = fmaf(wv.z, fmaxf(x0.z + y0.z, x1.z + y1.z), acc);
            acc = fmaf(wv.w, fmaxf(x0.w + y0.w, x1.w + y1.w), acc);
        }
    }
    __shared__ float red[8];
#pragma unroll
    for (int o = 16; o; o >>= 1) acc += __shfl_xor_sync(0xffffffffu, acc, o);
    if (!(tid & 31)) red[tid >> 5] = acc;
    __syncthreads();
    if (tid == 0) {
        float s = 0.f;
        for (int i = 0; i < 8; i++) s += red[i];
        part[bo*16 + tile] = s;
    }
}

__global__ void k_final2(const float* __restrict__ part, const float* __restrict__ rb,
                         float* __restrict__ out)
{
    int bo = threadIdx.x;
    float s = 0.f;
    for (int t = 0; t < 16; t++) s += part[bo*16 + t];
    out[bo] = s + rb[0];
}

// ------------------- host driver ---------------------------------------------
extern "C" void kernel_launch(void* const* d_in, const int* in_sizes, int n_in,
                              void* d_out, int out_size)
{
    const int*   q     = (const int*)d_in[0];
    const int*   a     = (const int*)d_in[1];
    const float* emb   = (const float*)d_in[2];
    const float* g1_wih = (const float*)d_in[3];
    const float* g1_whh = (const float*)d_in[4];
    const float* g1_bih = (const float*)d_in[5];
    const float* g1_bhh = (const float*)d_in[6];
    const float* g2_wih = (const float*)d_in[7];
    const float* g2_whh = (const float*)d_in[8];
    const float* g2_bih = (const float*)d_in[9];
    const float* g2_bhh = (const float*)d_in[10];
    const float* b1_w  = (const float*)d_in[11];
    const float* b1_b  = (const float*)d_in[12];
    const float* b2_w  = (const float*)d_in[13];
    const float* b2_b  = (const float*)d_in[14];
    const float* rank_w = (const float*)d_in[15];
    const float* rank_b = (const float*)d_in[16];
    float* out = (float*)d_out;

    float *X1, *GI1, *HS1, *CQ1, *CW2, *S, *CW, *QW, *Mx, *Q2C, *C2Q, *ATT, *GI2, *HS2, *C2, *AT2, *PART;
    cudaGetSymbolAddress((void**)&X1,  g_X1);
    cudaGetSymbolAddress((void**)&GI1, g_GI1);
    cudaGetSymbolAddress((void**)&HS1, g_HS1);
    cudaGetSymbolAddress((void**)&CQ1, g_CQ1);
    cudaGetSymbolAddress((void**)&CW2, g_CW2);
    cudaGetSymbolAddress((void**)&S,   g_S);
    cudaGetSymbolAddress((void**)&CW,  g_CW);
    cudaGetSymbolAddress((void**)&QW,  g_QW);
    cudaGetSymbolAddress((void**)&Mx,  g_M);
    cudaGetSymbolAddress((void**)&Q2C, g_Q2C);
    cudaGetSymbolAddress((void**)&C2Q, g_C2Q);
    cudaGetSymbolAddress((void**)&ATT, g_ATT);
    cudaGetSymbolAddress((void**)&GI2, g_GI2);
    cudaGetSymbolAddress((void**)&HS2, g_HS2);
    cudaGetSymbolAddress((void**)&C2,  g_C2);
    cudaGetSymbolAddress((void**)&AT2, g_AT2);
    cudaGetSymbolAddress((void**)&PART, g_PART);

    const int GSMEM = (2*128*36 + 2*64*36) * 4;     // 55296 B (NT and NN equal)
    const int PSMEM = (2*RPS*HPAD)*4 + 3*256*16*8;  // 131328 B
    cudaFuncSetAttribute(k_tc_nt, cudaFuncAttributeMaxDynamicSharedMemorySize, GSMEM);
    cudaFuncSetAttribute(k_tc_nn, cudaFuncAttributeMaxDynamicSharedMemorySize, GSMEM);
    cudaFuncSetAttribute(k_gru_persist, cudaFuncAttributeMaxDynamicSharedMemorySize, PSMEM);

    // 1) embedding
    k_embed<<<dim3(LSEQ, NR1), 64>>>(q, a, emb);

    // 2) GI1 = Wih1 @ X1[t]^T (tf32 TC, batched over t)
    k_tc_nt<<<dim3(12, 2, LSEQ), 256, GSMEM>>>(g1_wih, X1, GI1, g1_bih,
                                        1536, NR1, VEC, 0, (long)NR1*VEC, (long)1536*NR1);
    // 3) BiGRU-1: persistent cluster kernel
    k_gru_persist<<<96, 256, PSMEM>>>(GI1, HS1, g1_whh, g1_bhh, NR1);
    // 4) transpose to [seq][t][d]
    k_trans<<<dim3(LSEQ, 16, NR1/32), dim3(32, 8)>>>(HS1, CQ1, NR1);

    // 5) BiDAF-1 (c = question enc, q = article enc)
    const float* Qb1 = CQ1 + (size_t)32*LSEQ*LD;
    k_bidaf_pre<<<dim3(32, NR2), 256>>>(CQ1, Qb1, b1_w, CW, QW, CW2, 1);
    k_tc_nt<<<dim3(2, 4, NR2), 256, GSMEM>>>(CW2, Qb1, S, nullptr,
                                      256, 256, 512, (long)LSEQ*LD, (long)LSEQ*LD, (long)LSEQ*LSEQ);
    k_softmax<<<dim3(LSEQ, NR2), 256>>>(S, CW, QW, b1_b, Mx);
    k_q2c<<<NR2, 256>>>(Mx, CQ1, Q2C, 1);
    k_tc_nn<<<dim3(2, 8, NR2), 256, GSMEM>>>(S, Qb1, C2Q,
                                      256, 512, 256, (long)LSEQ*LSEQ, (long)LSEQ*LD, (long)LSEQ*LD);
    k_att<<<dim3(LSEQ, NR2), 512>>>(CQ1, C2Q, Q2C, ATT, 1);

    // 6) GI2 = Wih2 @ ATT[t]^T (tf32 TC, batched over t)
    k_tc_nt<<<dim3(12, 1, LSEQ), 256, GSMEM>>>(g2_wih, ATT, GI2, g2_bih,
                                        1536, NR2, F8, 0, (long)NR2*F8, (long)1536*NR2);
    // 7) BiGRU-2
    k_gru_persist<<<64, 256, PSMEM>>>(GI2, HS2, g2_whh, g2_bhh, NR2);
    k_trans<<<dim3(LSEQ, 16, NR2/32), dim3(32, 8)>>>(HS2, C2, NR2);

    // 8) BiDAF-2 (self)
    k_bidaf_pre<<<dim3(32, NR2), 256>>>(C2, C2, b2_w, CW, QW, CW2, 0);
    k_tc_nt<<<dim3(2, 4, NR2), 256, GSMEM>>>(CW2, C2, S, nullptr,
                                      256, 256, 512, (long)LSEQ*LD, (long)LSEQ*LD, (long)LSEQ*LSEQ);
    k_softmax<<<dim3(LSEQ, NR2), 256>>>(S, CW, QW, b2_b, Mx);
    k_q2c<<<NR2, 256>>>(Mx, C2, Q2C, 0);
    k_tc_nn<<<dim3(2, 8, NR2), 256, GSMEM>>>(S, C2, C2Q,
                                      256, 512, 256, (long)LSEQ*LSEQ, (long)LSEQ*LD, (long)LSEQ*LD);
    k_att<<<dim3(LSEQ, NR2), 512>>>(C2, C2Q, Q2C, AT2, 0);

    // 9) final
    k_final1<<<dim3(32, 16), 256>>>(ATT, AT2, rank_w, PART);
    k_final2<<<1, 32>>>(PART, rank_b, out);
}